// round 2
// baseline (speedup 1.0000x reference)
#include <cuda_runtime.h>

// DeepKoopman: B=1024,S=512,D=32,L=64,H=64,P=256
// Outputs concatenated: x_rec[B,S,D], x_dyn[B,S,D], x_pred[B,P,D], z[B,S,L], z_dyn[B,S,L]

namespace {
constexpr int Bn = 1024, Sn = 512, Dn = 32, Ln = 64, Hn = 64, Pn = 256;
constexpr int BS = Bn * Sn;                               // 524288
constexpr long OFF_XREC  = 0;
constexpr long OFF_XDYN  = (long)BS * Dn;                 // 16777216
constexpr long OFF_XPRED = OFF_XDYN * 2;                  // 33554432
constexpr long OFF_Z     = OFF_XPRED + (long)Bn * Pn * Dn;// 41943040
constexpr long OFF_ZDYN  = OFF_Z + (long)BS * Ln;         // 75497472
}

// scratch (device globals; no allocation allowed)
__device__ float g_Mpow[256][Ln * Ln];            // g_Mpow[p-1] = K^p (row-major)
__device__ float g_zpred[(long)Bn * Pn * Ln];     // [P,B,L] layout!

using u64 = unsigned long long;

__device__ __forceinline__ u64 f2fma(u64 a, u64 b, u64 c) {
    u64 d; asm("fma.rn.f32x2 %0, %1, %2, %3;" : "=l"(d) : "l"(a), "l"(b), "l"(c)); return d;
}
__device__ __forceinline__ u64 packdup(float x) {
    u64 d; asm("mov.b64 %0, {%1, %2};" : "=l"(d) : "f"(x), "f"(x)); return d;
}
__device__ __forceinline__ u64 pack2(float a, float b) {
    u64 d; asm("mov.b64 %0, {%1, %2};" : "=l"(d) : "f"(a), "f"(b)); return d;
}
__device__ __forceinline__ float2 unpk(u64 v) {
    float2 r; asm("mov.b64 {%0, %1}, %2;" : "=f"(r.x), "=f"(r.y) : "l"(v)); return r;
}

// acc[r2][j] (+)= At[k][r0+2*r2 .. +1] * Bt[k][c0+j], f32x2 pairs across rows.
template<int K, int NB, int AS, int BSTR>
__device__ __forceinline__ void gemm_f2(const float* At, const float* Bt,
                                        int r0, int c0, u64 (&acc)[4][NB]) {
#pragma unroll 16
    for (int k = 0; k < K; ++k) {
        ulonglong2 a01 = *reinterpret_cast<const ulonglong2*>(At + k * AS + r0);
        ulonglong2 a23 = *reinterpret_cast<const ulonglong2*>(At + k * AS + r0 + 4);
        u64 a2[4] = {a01.x, a01.y, a23.x, a23.y};
        float bv[NB];
        if (NB == 4) {
            float4 t = *reinterpret_cast<const float4*>(Bt + k * BSTR + c0);
            bv[0] = t.x; bv[1] = t.y; bv[2] = t.z; bv[3] = t.w;
        } else {
            float2 t = *reinterpret_cast<const float2*>(Bt + k * BSTR + c0);
            bv[0] = t.x; bv[1] = t.y;
        }
#pragma unroll
        for (int j = 0; j < NB; ++j) {
            u64 bb = packdup(bv[j]);
#pragma unroll
            for (int r2 = 0; r2 < 4; ++r2) acc[r2][j] = f2fma(a2[r2], bb, acc[r2][j]);
        }
    }
}

// ---------------------------------------------------------------------------
// Koopman power table (same as R1; small cost)
// ---------------------------------------------------------------------------
__device__ __forceinline__ void mm64_step(const float* sA, float* sB, float* gout, int tid) {
    float r[16];
#pragma unroll
    for (int t = 0; t < 16; ++t) {
        int o = tid + t * 256;
        int row = o >> 6, c = o & 63;
        float acc = 0.f;
#pragma unroll 8
        for (int k = 0; k < 64; ++k) acc += sA[row * 64 + k] * sB[k * 64 + c];
        r[t] = acc;
    }
    __syncthreads();
#pragma unroll
    for (int t = 0; t < 16; ++t) {
        int o = tid + t * 256;
        sB[o] = r[t];
        gout[o] = r[t];
    }
    __syncthreads();
}

__global__ void __launch_bounds__(256) kA1(const float* __restrict__ Kw) {
    __shared__ float sA[4096], sB[4096];
    int tid = threadIdx.x;
#pragma unroll
    for (int t = 0; t < 16; ++t) {
        int o = tid + t * 256;
        float v = Kw[o];
        sA[o] = v; sB[o] = v;
        g_Mpow[0][o] = v;
    }
    __syncthreads();
    for (int p = 2; p <= 8; ++p) mm64_step(sA, sB, g_Mpow[p - 1], tid);   // sB = K^8
#pragma unroll
    for (int t = 0; t < 16; ++t) { int o = tid + t * 256; sA[o] = sB[o]; }
    __syncthreads();
    for (int q = 2; q <= 8; ++q) mm64_step(sA, sB, g_Mpow[8 * q - 1], tid); // sB = K^64
#pragma unroll
    for (int t = 0; t < 16; ++t) { int o = tid + t * 256; sA[o] = sB[o]; }
    __syncthreads();
    mm64_step(sA, sB, g_Mpow[127], tid);  // K^128
    mm64_step(sA, sB, g_Mpow[191], tid);  // K^192
}

__device__ __forceinline__ void mm64_gg(const float* __restrict__ ga, const float* __restrict__ gb,
                                        float* __restrict__ gd, float* sA, float* sB, int tid) {
#pragma unroll
    for (int t = 0; t < 16; ++t) {
        int o = tid + t * 256;
        sA[o] = ga[o]; sB[o] = gb[o];
    }
    __syncthreads();
#pragma unroll
    for (int t = 0; t < 16; ++t) {
        int o = tid + t * 256;
        int row = o >> 6, c = o & 63;
        float acc = 0.f;
#pragma unroll 8
        for (int k = 0; k < 64; ++k) acc += sA[row * 64 + k] * sB[k * 64 + c];
        gd[o] = acc;
    }
}

__global__ void __launch_bounds__(256) kA2a() {
    int q = blockIdx.x / 7 + 1, r = blockIdx.x % 7 + 1;
    __shared__ float sA[4096], sB[4096];
    mm64_gg(g_Mpow[8 * q - 1], g_Mpow[r - 1], g_Mpow[8 * q + r - 1], sA, sB, threadIdx.x);
}

__global__ void __launch_bounds__(256) kA2b() {
    int t = blockIdx.x / 64 + 1, m = blockIdx.x % 64 + 1;
    if (m == 64 && t <= 2) return;
    __shared__ float sA[4096], sB[4096];
    mm64_gg(g_Mpow[64 * t - 1], g_Mpow[m - 1], g_Mpow[64 * t + m - 1], sA, sB, threadIdx.x);
}

// ---------------------------------------------------------------------------
// Encoder: x -> z, z_dyn.  Tiled: 128 rows/block, 256 threads, 8x4 per thread.
// smem: A (32KB, activations transposed) + Bw (16KB, weights transposed)
// ---------------------------------------------------------------------------
__global__ void __launch_bounds__(256) kEnc(
    const float* __restrict__ x,
    const float* __restrict__ ew1, const float* __restrict__ eb1,
    const float* __restrict__ ew2, const float* __restrict__ eb2,
    const float* __restrict__ Kw,
    float* __restrict__ out)
{
    __shared__ float A[64 * 128];   // 32KB
    __shared__ float Bw[64 * 64];   // 16KB
    int tid = threadIdx.x;
    long row0 = (long)blockIdx.x * 128;
    int r0 = (tid & 15) * 8;
    int c0 = (tid >> 4) * 4;

    // Load x tile transposed: A[k][row], k<32
    {
        int kq = tid & 7, r = tid >> 3;          // 32 rows per pass
#pragma unroll
        for (int it = 0; it < 4; ++it, r += 32) {
            float4 v = *reinterpret_cast<const float4*>(x + (row0 + r) * Dn + kq * 4);
            A[(kq * 4 + 0) * 128 + r] = v.x;
            A[(kq * 4 + 1) * 128 + r] = v.y;
            A[(kq * 4 + 2) * 128 + r] = v.z;
            A[(kq * 4 + 3) * 128 + r] = v.w;
        }
    }
    // Load ew1 transposed: Bw[k][j], k<32, j<64
    {
        int kq = tid & 7, j = tid >> 3;          // 32 j per pass
#pragma unroll
        for (int it = 0; it < 2; ++it, j += 32) {
            float4 v = *reinterpret_cast<const float4*>(ew1 + j * Dn + kq * 4);
            Bw[(kq * 4 + 0) * 64 + j] = v.x;
            Bw[(kq * 4 + 1) * 64 + j] = v.y;
            Bw[(kq * 4 + 2) * 64 + j] = v.z;
            Bw[(kq * 4 + 3) * 64 + j] = v.w;
        }
    }
    __syncthreads();

    // Phase 1: h = relu(x@W1^T + b1), tile C[128][64]
    u64 acc[4][4];
#pragma unroll
    for (int j = 0; j < 4; ++j) {
        u64 b = packdup(__ldg(eb1 + c0 + j));
#pragma unroll
        for (int r2 = 0; r2 < 4; ++r2) acc[r2][j] = b;
    }
    gemm_f2<32, 4, 128, 64>(A, Bw, r0, c0, acc);
    __syncthreads();

    // relu + store h transposed into A; load ew2 transposed into Bw
#pragma unroll
    for (int j = 0; j < 4; ++j) {
        u64 v[4];
#pragma unroll
        for (int r2 = 0; r2 < 4; ++r2) {
            float2 f = unpk(acc[r2][j]);
            v[r2] = pack2(fmaxf(f.x, 0.f), fmaxf(f.y, 0.f));
        }
        *reinterpret_cast<ulonglong2*>(&A[(c0 + j) * 128 + r0])     = make_ulonglong2(v[0], v[1]);
        *reinterpret_cast<ulonglong2*>(&A[(c0 + j) * 128 + r0 + 4]) = make_ulonglong2(v[2], v[3]);
    }
    {
        int jq = tid & 15, l = tid >> 4;         // ew2[l][j] -> Bw[j][l]
#pragma unroll
        for (int it = 0; it < 4; ++it, l += 16) {
            float4 v = *reinterpret_cast<const float4*>(ew2 + l * Hn + jq * 4);
            Bw[(jq * 4 + 0) * 64 + l] = v.x;
            Bw[(jq * 4 + 1) * 64 + l] = v.y;
            Bw[(jq * 4 + 2) * 64 + l] = v.z;
            Bw[(jq * 4 + 3) * 64 + l] = v.w;
        }
    }
    __syncthreads();

    // Phase 2: z = h@W2^T + b2
#pragma unroll
    for (int j = 0; j < 4; ++j) {
        u64 b = packdup(__ldg(eb2 + c0 + j));
#pragma unroll
        for (int r2 = 0; r2 < 4; ++r2) acc[r2][j] = b;
    }
    gemm_f2<64, 4, 128, 64>(A, Bw, r0, c0, acc);

    // write z to global
    {
        float f[4][4][2];
#pragma unroll
        for (int r2 = 0; r2 < 4; ++r2)
#pragma unroll
            for (int j = 0; j < 4; ++j) {
                float2 p = unpk(acc[r2][j]);
                f[r2][j][0] = p.x; f[r2][j][1] = p.y;
            }
#pragma unroll
        for (int rr = 0; rr < 8; ++rr) {
            int r2 = rr >> 1, s = rr & 1;
            *reinterpret_cast<float4*>(out + OFF_Z + (row0 + r0 + rr) * Ln + c0) =
                make_float4(f[r2][0][s], f[r2][1][s], f[r2][2][s], f[r2][3][s]);
        }
    }
    __syncthreads();

    // store z transposed into A; load K transposed into Bw
#pragma unroll
    for (int j = 0; j < 4; ++j) {
        *reinterpret_cast<ulonglong2*>(&A[(c0 + j) * 128 + r0])     = make_ulonglong2(acc[0][j], acc[1][j]);
        *reinterpret_cast<ulonglong2*>(&A[(c0 + j) * 128 + r0 + 4]) = make_ulonglong2(acc[2][j], acc[3][j]);
    }
    {
        int lq = tid & 15, lp = tid >> 4;        // Kw[l'][l] -> Bw[l][l']
#pragma unroll
        for (int it = 0; it < 4; ++it, lp += 16) {
            float4 v = *reinterpret_cast<const float4*>(Kw + lp * Ln + lq * 4);
            Bw[(lq * 4 + 0) * 64 + lp] = v.x;
            Bw[(lq * 4 + 1) * 64 + lp] = v.y;
            Bw[(lq * 4 + 2) * 64 + lp] = v.z;
            Bw[(lq * 4 + 3) * 64 + lp] = v.w;
        }
    }
    __syncthreads();

    // Phase 3: z_dyn = z@K^T
#pragma unroll
    for (int j = 0; j < 4; ++j)
#pragma unroll
        for (int r2 = 0; r2 < 4; ++r2) acc[r2][j] = 0ull;
    gemm_f2<64, 4, 128, 64>(A, Bw, r0, c0, acc);
    {
        float f[4][4][2];
#pragma unroll
        for (int r2 = 0; r2 < 4; ++r2)
#pragma unroll
            for (int j = 0; j < 4; ++j) {
                float2 p = unpk(acc[r2][j]);
                f[r2][j][0] = p.x; f[r2][j][1] = p.y;
            }
#pragma unroll
        for (int rr = 0; rr < 8; ++rr) {
            int r2 = rr >> 1, s = rr & 1;
            *reinterpret_cast<float4*>(out + OFF_ZDYN + (row0 + r0 + rr) * Ln + c0) =
                make_float4(f[r2][0][s], f[r2][1][s], f[r2][2][s], f[r2][3][s]);
        }
    }
}

// ---------------------------------------------------------------------------
// Pred rollout: g_zpred[p][b][:] = z_last[b] @ (K^(p+1))^T
// Block: fixed p, 128 b's.  grid = 256*8
// ---------------------------------------------------------------------------
__global__ void __launch_bounds__(256) kPredZ(const float* __restrict__ zfull) {
    __shared__ float A[64 * 128];
    __shared__ float Bw[64 * 64];
    int tid = threadIdx.x;
    int p = blockIdx.x >> 3;
    int b0 = (blockIdx.x & 7) * 128;
    int r0 = (tid & 15) * 8;
    int c0 = (tid >> 4) * 4;

    // load z_last rows transposed
    {
        int kq = tid & 15, r = tid >> 4;
#pragma unroll
        for (int it = 0; it < 8; ++it, r += 16) {
            float4 v = *reinterpret_cast<const float4*>(
                zfull + ((long)(b0 + r) * Sn + (Sn - 1)) * Ln + kq * 4);
            A[(kq * 4 + 0) * 128 + r] = v.x;
            A[(kq * 4 + 1) * 128 + r] = v.y;
            A[(kq * 4 + 2) * 128 + r] = v.z;
            A[(kq * 4 + 3) * 128 + r] = v.w;
        }
    }
    // load M = K^(p+1) transposed: M[l'][l] -> Bw[l][l']
    {
        int lq = tid & 15, lp = tid >> 4;
        const float* M = g_Mpow[p];
#pragma unroll
        for (int it = 0; it < 4; ++it, lp += 16) {
            float4 v = *reinterpret_cast<const float4*>(M + lp * Ln + lq * 4);
            Bw[(lq * 4 + 0) * 64 + lp] = v.x;
            Bw[(lq * 4 + 1) * 64 + lp] = v.y;
            Bw[(lq * 4 + 2) * 64 + lp] = v.z;
            Bw[(lq * 4 + 3) * 64 + lp] = v.w;
        }
    }
    __syncthreads();

    u64 acc[4][4];
#pragma unroll
    for (int j = 0; j < 4; ++j)
#pragma unroll
        for (int r2 = 0; r2 < 4; ++r2) acc[r2][j] = 0ull;
    gemm_f2<64, 4, 128, 64>(A, Bw, r0, c0, acc);

    float f[4][4][2];
#pragma unroll
    for (int r2 = 0; r2 < 4; ++r2)
#pragma unroll
        for (int j = 0; j < 4; ++j) {
            float2 q = unpk(acc[r2][j]);
            f[r2][j][0] = q.x; f[r2][j][1] = q.y;
        }
#pragma unroll
    for (int rr = 0; rr < 8; ++rr) {
        int r2 = rr >> 1, s = rr & 1;
        *reinterpret_cast<float4*>(g_zpred + ((long)p * Bn + b0 + r0 + rr) * Ln + c0) =
            make_float4(f[r2][0][s], f[r2][1][s], f[r2][2][s], f[r2][3][s]);
    }
}

// ---------------------------------------------------------------------------
// Decoder: xout = relu(zin@W1^T + b1) @ W2^T + b2.  Tiled like kEnc.
// is_pred: input rows are [p][b]; output row remapped to b*P+p.
// ---------------------------------------------------------------------------
__global__ void __launch_bounds__(256) kDec(
    const float* __restrict__ zin, float* __restrict__ xout,
    const float* __restrict__ dw1, const float* __restrict__ db1,
    const float* __restrict__ dw2, const float* __restrict__ db2,
    int is_pred)
{
    __shared__ float A[64 * 128];
    __shared__ float Bw[64 * 64];
    int tid = threadIdx.x;
    long row0 = (long)blockIdx.x * 128;
    int r0 = (tid & 15) * 8;
    int c0 = (tid >> 4) * 4;

    const float* zbase = zin ? zin : g_zpred;

    // load zin tile transposed
    {
        int kq = tid & 15, r = tid >> 4;
#pragma unroll
        for (int it = 0; it < 8; ++it, r += 16) {
            float4 v = *reinterpret_cast<const float4*>(zbase + (row0 + r) * Ln + kq * 4);
            A[(kq * 4 + 0) * 128 + r] = v.x;
            A[(kq * 4 + 1) * 128 + r] = v.y;
            A[(kq * 4 + 2) * 128 + r] = v.z;
            A[(kq * 4 + 3) * 128 + r] = v.w;
        }
    }
    // load dw1 transposed: dw1[j][k] -> Bw[k][j]
    {
        int kq = tid & 15, j = tid >> 4;
#pragma unroll
        for (int it = 0; it < 4; ++it, j += 16) {
            float4 v = *reinterpret_cast<const float4*>(dw1 + j * Ln + kq * 4);
            Bw[(kq * 4 + 0) * 64 + j] = v.x;
            Bw[(kq * 4 + 1) * 64 + j] = v.y;
            Bw[(kq * 4 + 2) * 64 + j] = v.z;
            Bw[(kq * 4 + 3) * 64 + j] = v.w;
        }
    }
    __syncthreads();

    // Phase 1: h = relu(z@W1^T + b1)
    u64 acc[4][4];
#pragma unroll
    for (int j = 0; j < 4; ++j) {
        u64 b = packdup(__ldg(db1 + c0 + j));
#pragma unroll
        for (int r2 = 0; r2 < 4; ++r2) acc[r2][j] = b;
    }
    gemm_f2<64, 4, 128, 64>(A, Bw, r0, c0, acc);
    __syncthreads();

    // relu + store h transposed; load dw2 transposed: dw2[d][j] -> Bw2[j][d] (stride 32)
#pragma unroll
    for (int j = 0; j < 4; ++j) {
        u64 v[4];
#pragma unroll
        for (int r2 = 0; r2 < 4; ++r2) {
            float2 p = unpk(acc[r2][j]);
            v[r2] = pack2(fmaxf(p.x, 0.f), fmaxf(p.y, 0.f));
        }
        *reinterpret_cast<ulonglong2*>(&A[(c0 + j) * 128 + r0])     = make_ulonglong2(v[0], v[1]);
        *reinterpret_cast<ulonglong2*>(&A[(c0 + j) * 128 + r0 + 4]) = make_ulonglong2(v[2], v[3]);
    }
    {
        int jq = tid & 15, d = tid >> 4;          // 16 d per pass
#pragma unroll
        for (int it = 0; it < 2; ++it, d += 16) {
            float4 v = *reinterpret_cast<const float4*>(dw2 + d * Hn + jq * 4);
            Bw[(jq * 4 + 0) * 32 + d] = v.x;
            Bw[(jq * 4 + 1) * 32 + d] = v.y;
            Bw[(jq * 4 + 2) * 32 + d] = v.z;
            Bw[(jq * 4 + 3) * 32 + d] = v.w;
        }
    }
    __syncthreads();

    // Phase 2: out = h@W2^T + b2, tile 8 rows x 2 cols
    int d0 = (tid >> 4) * 2;
    u64 acc2[4][2];
#pragma unroll
    for (int j = 0; j < 2; ++j) {
        u64 b = packdup(__ldg(db2 + d0 + j));
#pragma unroll
        for (int r2 = 0; r2 < 4; ++r2) acc2[r2][j] = b;
    }
    gemm_f2<64, 2, 128, 32>(A, Bw, r0, d0, acc2);

    // write out (float2 per row), with optional pred row remap
#pragma unroll
    for (int rr = 0; rr < 8; ++rr) {
        int r2 = rr >> 1, s = rr & 1;
        long grow = row0 + r0 + rr;
        long orow = grow;
        if (is_pred) orow = ((grow & 1023) << 8) | (grow >> 10);  // b*P + p
        float2 p0 = unpk(acc2[r2][0]);
        float2 p1 = unpk(acc2[r2][1]);
        float2 v = s ? make_float2(p0.y, p1.y) : make_float2(p0.x, p1.x);
        *reinterpret_cast<float2*>(xout + orow * Dn + d0) = v;
    }
}

// ---------------------------------------------------------------------------
extern "C" void kernel_launch(void* const* d_in, const int* in_sizes, int n_in,
                              void* d_out, int out_size) {
    const float* x   = (const float*)d_in[0];
    const float* ew1 = (const float*)d_in[1];
    const float* eb1 = (const float*)d_in[2];
    const float* ew2 = (const float*)d_in[3];
    const float* eb2 = (const float*)d_in[4];
    const float* dw1 = (const float*)d_in[5];
    const float* db1 = (const float*)d_in[6];
    const float* dw2 = (const float*)d_in[7];
    const float* db2 = (const float*)d_in[8];
    const float* Kw  = (const float*)d_in[9];
    float* out = (float*)d_out;

    kA1<<<1, 256>>>(Kw);
    kA2a<<<49, 256>>>();
    kA2b<<<192, 256>>>();

    kEnc<<<BS / 128, 256>>>(x, ew1, eb1, ew2, eb2, Kw, out);

    kPredZ<<<Pn * 8, 256>>>(out + OFF_Z);

    kDec<<<BS / 128, 256>>>(out + OFF_Z,    out + OFF_XREC,  dw1, db1, dw2, db2, 0);
    kDec<<<BS / 128, 256>>>(out + OFF_ZDYN, out + OFF_XDYN,  dw1, db1, dw2, db2, 0);
    kDec<<<(Bn * Pn) / 128, 256>>>(nullptr, out + OFF_XPRED, dw1, db1, dw2, db2, 1);
}

// round 4
// speedup vs baseline: 1.4864x; 1.4864x over previous
#include <cuda_runtime.h>

// DeepKoopman: B=1024,S=512,D=32,L=64,H=64,P=256
// Outputs concatenated: x_rec[B,S,D], x_dyn[B,S,D], x_pred[B,P,D], z[B,S,L], z_dyn[B,S,L]

namespace {
constexpr int Bn = 1024, Sn = 512, Dn = 32, Ln = 64, Hn = 64, Pn = 256;
constexpr int BS = Bn * Sn;                               // 524288
constexpr long OFF_XREC  = 0;
constexpr long OFF_XDYN  = (long)BS * Dn;                 // 16777216
constexpr long OFF_XPRED = OFF_XDYN * 2;                  // 33554432
constexpr long OFF_Z     = OFF_XPRED + (long)Bn * Pn * Dn;// 41943040
constexpr long OFF_ZDYN  = OFF_Z + (long)BS * Ln;         // 75497472
}

__device__ float g_Mpow[256][Ln * Ln];            // g_Mpow[p-1] = K^p (row-major)
__device__ float g_zpred[(long)Bn * Pn * Ln];     // [P,B,L] layout

using u64 = unsigned long long;

__device__ __forceinline__ u64 f2fma(u64 a, u64 b, u64 c) {
    u64 d; asm("fma.rn.f32x2 %0, %1, %2, %3;" : "=l"(d) : "l"(a), "l"(b), "l"(c)); return d;
}
__device__ __forceinline__ u64 packdup(float x) {
    u64 d; asm("mov.b64 %0, {%1, %2};" : "=l"(d) : "f"(x), "f"(x)); return d;
}
__device__ __forceinline__ float2 unpk(u64 v) {
    float2 r; asm("mov.b64 {%0, %1}, %2;" : "=f"(r.x), "=f"(r.y) : "l"(v)); return r;
}

// ---------------------------------------------------------------------------
// Core: acc[r][j] = f32x2 pair over cols (c0+2j, c0+2j+1), rows lane*4+r.
// lane: rows lane*4..lane*4+3 (conflict-free LDS.128, all 32 lanes distinct rows)
// warp: cols c0 = warp*2*NBP. B loads are warp-uniform (broadcast).
// ---------------------------------------------------------------------------
template<int KK, int NBP, int BSTR>
__device__ __forceinline__ void gemm2(const float* At, const float* Bt,
                                      int lane, int c0, u64 (&acc)[4][NBP]) {
#pragma unroll 8
    for (int k = 0; k < KK; ++k) {
        float4 a4 = *reinterpret_cast<const float4*>(At + k * 128 + lane * 4);
        u64 ad0 = packdup(a4.x), ad1 = packdup(a4.y), ad2 = packdup(a4.z), ad3 = packdup(a4.w);
        u64 bp[NBP];
        ulonglong2 b01 = *reinterpret_cast<const ulonglong2*>(Bt + k * BSTR + c0);
        bp[0] = b01.x; bp[1] = b01.y;
        if (NBP == 4) {
            ulonglong2 b23 = *reinterpret_cast<const ulonglong2*>(Bt + k * BSTR + c0 + 4);
            bp[2] = b23.x; bp[3] = b23.y;
        }
#pragma unroll
        for (int j = 0; j < NBP; ++j) {
            acc[0][j] = f2fma(ad0, bp[j], acc[0][j]);
            acc[1][j] = f2fma(ad1, bp[j], acc[1][j]);
            acc[2][j] = f2fma(ad2, bp[j], acc[2][j]);
            acc[3][j] = f2fma(ad3, bp[j], acc[3][j]);
        }
    }
}

// transpose-store acc tile into At[col][128] (+optional relu). Conflict-free STS.128.
template<bool RELU>
__device__ __forceinline__ void storeT(float* At, int lane, int c0, const u64 (&acc)[4][4]) {
#pragma unroll
    for (int j = 0; j < 4; ++j) {
        float2 p0 = unpk(acc[0][j]), p1 = unpk(acc[1][j]), p2 = unpk(acc[2][j]), p3 = unpk(acc[3][j]);
        float4 lo = make_float4(p0.x, p1.x, p2.x, p3.x);
        float4 hi = make_float4(p0.y, p1.y, p2.y, p3.y);
        if (RELU) {
            lo.x = fmaxf(lo.x, 0.f); lo.y = fmaxf(lo.y, 0.f); lo.z = fmaxf(lo.z, 0.f); lo.w = fmaxf(lo.w, 0.f);
            hi.x = fmaxf(hi.x, 0.f); hi.y = fmaxf(hi.y, 0.f); hi.z = fmaxf(hi.z, 0.f); hi.w = fmaxf(hi.w, 0.f);
        }
        *reinterpret_cast<float4*>(At + (c0 + 2 * j)     * 128 + lane * 4) = lo;
        *reinterpret_cast<float4*>(At + (c0 + 2 * j + 1) * 128 + lane * 4) = hi;
    }
}

// load 64x64 row-major W[a][b] -> Bt[b][a] (stride 64)
__device__ __forceinline__ void loadW64T(const float* __restrict__ W, float* Bt, int tid) {
    int bq = tid & 15, a = tid >> 4;
#pragma unroll
    for (int it = 0; it < 4; ++it, a += 16) {
        float4 v = *reinterpret_cast<const float4*>(W + a * 64 + bq * 4);
        Bt[(bq * 4 + 0) * 64 + a] = v.x;
        Bt[(bq * 4 + 1) * 64 + a] = v.y;
        Bt[(bq * 4 + 2) * 64 + a] = v.z;
        Bt[(bq * 4 + 3) * 64 + a] = v.w;
    }
}

// load rows [row0..row0+128) of Z[.][64] -> At[k][128]
__device__ __forceinline__ void loadZ128T(const float* __restrict__ Z, long row0, float* At, int tid) {
    int kq = tid & 15, r = tid >> 4;
#pragma unroll
    for (int it = 0; it < 8; ++it, r += 16) {
        float4 v = *reinterpret_cast<const float4*>(Z + (row0 + r) * 64 + kq * 4);
        At[(kq * 4 + 0) * 128 + r] = v.x;
        At[(kq * 4 + 1) * 128 + r] = v.y;
        At[(kq * 4 + 2) * 128 + r] = v.z;
        At[(kq * 4 + 3) * 128 + r] = v.w;
    }
}

// ---------------------------------------------------------------------------
// Koopman power table
// ---------------------------------------------------------------------------
__device__ __forceinline__ void mm64_step(const float* sA, float* sB, float* gout, int tid) {
    float r[16];
#pragma unroll
    for (int t = 0; t < 16; ++t) {
        int o = tid + t * 256;
        int row = o >> 6, c = o & 63;
        float acc = 0.f;
#pragma unroll 8
        for (int k = 0; k < 64; ++k) acc += sA[row * 64 + k] * sB[k * 64 + c];
        r[t] = acc;
    }
    __syncthreads();
#pragma unroll
    for (int t = 0; t < 16; ++t) {
        int o = tid + t * 256;
        sB[o] = r[t];
        gout[o] = r[t];
    }
    __syncthreads();
}

__global__ void __launch_bounds__(256) kA1(const float* __restrict__ Kw) {
    __shared__ float sA[4096], sB[4096];
    int tid = threadIdx.x;
#pragma unroll
    for (int t = 0; t < 16; ++t) {
        int o = tid + t * 256;
        float v = Kw[o];
        sA[o] = v; sB[o] = v;
        g_Mpow[0][o] = v;
    }
    __syncthreads();
    for (int p = 2; p <= 8; ++p) mm64_step(sA, sB, g_Mpow[p - 1], tid);     // sB = K^8
#pragma unroll
    for (int t = 0; t < 16; ++t) { int o = tid + t * 256; sA[o] = sB[o]; }
    __syncthreads();
    for (int q = 2; q <= 8; ++q) mm64_step(sA, sB, g_Mpow[8 * q - 1], tid); // sB = K^64
#pragma unroll
    for (int t = 0; t < 16; ++t) { int o = tid + t * 256; sA[o] = sB[o]; }
    __syncthreads();
    mm64_step(sA, sB, g_Mpow[127], tid);  // K^128
    mm64_step(sA, sB, g_Mpow[191], tid);  // K^192
}

__device__ __forceinline__ void mm64_gg(const float* __restrict__ ga, const float* __restrict__ gb,
                                        float* __restrict__ gd, float* sA, float* sB, int tid) {
#pragma unroll
    for (int t = 0; t < 16; ++t) {
        int o = tid + t * 256;
        sA[o] = ga[o]; sB[o] = gb[o];
    }
    __syncthreads();
#pragma unroll
    for (int t = 0; t < 16; ++t) {
        int o = tid + t * 256;
        int row = o >> 6, c = o & 63;
        float acc = 0.f;
#pragma unroll 8
        for (int k = 0; k < 64; ++k) acc += sA[row * 64 + k] * sB[k * 64 + c];
        gd[o] = acc;
    }
}

__global__ void __launch_bounds__(256) kA2a() {
    int q = blockIdx.x / 7 + 1, r = blockIdx.x % 7 + 1;
    __shared__ float sA[4096], sB[4096];
    mm64_gg(g_Mpow[8 * q - 1], g_Mpow[r - 1], g_Mpow[8 * q + r - 1], sA, sB, threadIdx.x);
}

__global__ void __launch_bounds__(256) kA2b() {
    int t = blockIdx.x / 64 + 1, m = blockIdx.x % 64 + 1;
    if (m == 64 && t <= 2) return;
    __shared__ float sA[4096], sB[4096];
    mm64_gg(g_Mpow[64 * t - 1], g_Mpow[m - 1], g_Mpow[64 * t + m - 1], sA, sB, threadIdx.x);
}

// ---------------------------------------------------------------------------
// Encoder: x -> z, z_dyn.  128 rows/block, 256 threads.
// ---------------------------------------------------------------------------
__global__ void __launch_bounds__(256) kEnc(
    const float* __restrict__ x,
    const float* __restrict__ ew1, const float* __restrict__ eb1,
    const float* __restrict__ ew2, const float* __restrict__ eb2,
    const float* __restrict__ Kw,
    float* __restrict__ out)
{
    __shared__ float At[64 * 128];   // 32KB
    __shared__ float Bt[64 * 64];    // 16KB
    int tid = threadIdx.x;
    int lane = tid & 31;
    int c0 = (tid >> 5) * 8;
    long row0 = (long)blockIdx.x * 128;

    // x rows -> At[k<32][128]
    {
        int kq = tid & 7, r = tid >> 3;
#pragma unroll
        for (int it = 0; it < 4; ++it, r += 32) {
            float4 v = *reinterpret_cast<const float4*>(x + (row0 + r) * Dn + kq * 4);
            At[(kq * 4 + 0) * 128 + r] = v.x;
            At[(kq * 4 + 1) * 128 + r] = v.y;
            At[(kq * 4 + 2) * 128 + r] = v.z;
            At[(kq * 4 + 3) * 128 + r] = v.w;
        }
    }
    // ew1[64][32] -> Bt[k<32][64]
    {
        int kq = tid & 7, j = tid >> 3;
#pragma unroll
        for (int it = 0; it < 2; ++it, j += 32) {
            float4 v = *reinterpret_cast<const float4*>(ew1 + j * Dn + kq * 4);
            Bt[(kq * 4 + 0) * 64 + j] = v.x;
            Bt[(kq * 4 + 1) * 64 + j] = v.y;
            Bt[(kq * 4 + 2) * 64 + j] = v.z;
            Bt[(kq * 4 + 3) * 64 + j] = v.w;
        }
    }
    __syncthreads();

    // Phase 1: h = relu(x@W1^T + b1)
    u64 acc[4][4];
    {
        ulonglong2 b01 = *reinterpret_cast<const ulonglong2*>(eb1 + c0);
        ulonglong2 b23 = *reinterpret_cast<const ulonglong2*>(eb1 + c0 + 4);
#pragma unroll
        for (int r = 0; r < 4; ++r) { acc[r][0] = b01.x; acc[r][1] = b01.y; acc[r][2] = b23.x; acc[r][3] = b23.y; }
    }
    gemm2<32, 4, 64>(At, Bt, lane, c0, acc);
    __syncthreads();

    // h -> At transposed (relu); ew2[64][64] -> Bt[j][l]
    storeT<true>(At, lane, c0, acc);
    loadW64T(ew2, Bt, tid);
    __syncthreads();

    // Phase 2: z = h@W2^T + b2
    {
        ulonglong2 b01 = *reinterpret_cast<const ulonglong2*>(eb2 + c0);
        ulonglong2 b23 = *reinterpret_cast<const ulonglong2*>(eb2 + c0 + 4);
#pragma unroll
        for (int r = 0; r < 4; ++r) { acc[r][0] = b01.x; acc[r][1] = b01.y; acc[r][2] = b23.x; acc[r][3] = b23.y; }
    }
    gemm2<64, 4, 64>(At, Bt, lane, c0, acc);

    // z -> global (row-major pairs are native)
#pragma unroll
    for (int r = 0; r < 4; ++r) {
        long row = row0 + lane * 4 + r;
        *reinterpret_cast<ulonglong2*>(out + OFF_Z + row * Ln + c0)     = make_ulonglong2(acc[r][0], acc[r][1]);
        *reinterpret_cast<ulonglong2*>(out + OFF_Z + row * Ln + c0 + 4) = make_ulonglong2(acc[r][2], acc[r][3]);
    }
    __syncthreads();

    // z -> At transposed; K -> Bt transposed
    storeT<false>(At, lane, c0, acc);
    loadW64T(Kw, Bt, tid);
    __syncthreads();

    // Phase 3: z_dyn = z@K^T
#pragma unroll
    for (int j = 0; j < 4; ++j)
#pragma unroll
        for (int r = 0; r < 4; ++r) acc[r][j] = 0ull;
    gemm2<64, 4, 64>(At, Bt, lane, c0, acc);
#pragma unroll
    for (int r = 0; r < 4; ++r) {
        long row = row0 + lane * 4 + r;
        *reinterpret_cast<ulonglong2*>(out + OFF_ZDYN + row * Ln + c0)     = make_ulonglong2(acc[r][0], acc[r][1]);
        *reinterpret_cast<ulonglong2*>(out + OFF_ZDYN + row * Ln + c0 + 4) = make_ulonglong2(acc[r][2], acc[r][3]);
    }
}

// ---------------------------------------------------------------------------
// Pred rollout: g_zpred[p][b][:] = z_last[b] @ (K^(p+1))^T.  grid = 256*8
// ---------------------------------------------------------------------------
__global__ void __launch_bounds__(256) kPredZ(const float* __restrict__ zfull) {
    __shared__ float At[64 * 128];
    __shared__ float Bt[64 * 64];
    int tid = threadIdx.x;
    int lane = tid & 31;
    int c0 = (tid >> 5) * 8;
    int p = blockIdx.x >> 3;
    int b0 = (blockIdx.x & 7) * 128;

    // z_last rows -> At[k][128]
    {
        int kq = tid & 15, r = tid >> 4;
#pragma unroll
        for (int it = 0; it < 8; ++it, r += 16) {
            float4 v = *reinterpret_cast<const float4*>(
                zfull + ((long)(b0 + r) * Sn + (Sn - 1)) * Ln + kq * 4);
            At[(kq * 4 + 0) * 128 + r] = v.x;
            At[(kq * 4 + 1) * 128 + r] = v.y;
            At[(kq * 4 + 2) * 128 + r] = v.z;
            At[(kq * 4 + 3) * 128 + r] = v.w;
        }
    }
    loadW64T(g_Mpow[p], Bt, tid);
    __syncthreads();

    u64 acc[4][4];
#pragma unroll
    for (int j = 0; j < 4; ++j)
#pragma unroll
        for (int r = 0; r < 4; ++r) acc[r][j] = 0ull;
    gemm2<64, 4, 64>(At, Bt, lane, c0, acc);

#pragma unroll
    for (int r = 0; r < 4; ++r) {
        long row = (long)p * Bn + b0 + lane * 4 + r;
        *reinterpret_cast<ulonglong2*>(g_zpred + row * Ln + c0)     = make_ulonglong2(acc[r][0], acc[r][1]);
        *reinterpret_cast<ulonglong2*>(g_zpred + row * Ln + c0 + 4) = make_ulonglong2(acc[r][2], acc[r][3]);
    }
}

// ---------------------------------------------------------------------------
// Decoder: xout = relu(zin@W1^T + b1) @ W2^T + b2.  128 rows/block.
// ---------------------------------------------------------------------------
__global__ void __launch_bounds__(256) kDec(
    const float* __restrict__ zin, float* __restrict__ xout,
    const float* __restrict__ dw1, const float* __restrict__ db1,
    const float* __restrict__ dw2, const float* __restrict__ db2,
    int is_pred)
{
    __shared__ float At[64 * 128];
    __shared__ float Bt[64 * 64];
    int tid = threadIdx.x;
    int lane = tid & 31;
    int c0 = (tid >> 5) * 8;
    long row0 = (long)blockIdx.x * 128;

    const float* zbase = zin ? zin : g_zpred;
    loadZ128T(zbase, row0, At, tid);
    loadW64T(dw1, Bt, tid);
    __syncthreads();

    // Phase 1: h = relu(z@W1^T + b1)
    u64 acc[4][4];
    {
        ulonglong2 b01 = *reinterpret_cast<const ulonglong2*>(db1 + c0);
        ulonglong2 b23 = *reinterpret_cast<const ulonglong2*>(db1 + c0 + 4);
#pragma unroll
        for (int r = 0; r < 4; ++r) { acc[r][0] = b01.x; acc[r][1] = b01.y; acc[r][2] = b23.x; acc[r][3] = b23.y; }
    }
    gemm2<64, 4, 64>(At, Bt, lane, c0, acc);
    __syncthreads();

    // h -> At transposed (relu); dw2[32][64] -> Bt[j][d] (stride 32)
    storeT<true>(At, lane, c0, acc);
    {
        int jq = tid & 15, d = tid >> 4;
#pragma unroll
        for (int it = 0; it < 2; ++it, d += 16) {
            float4 v = *reinterpret_cast<const float4*>(dw2 + d * Hn + jq * 4);
            Bt[(jq * 4 + 0) * 32 + d] = v.x;
            Bt[(jq * 4 + 1) * 32 + d] = v.y;
            Bt[(jq * 4 + 2) * 32 + d] = v.z;
            Bt[(jq * 4 + 3) * 32 + d] = v.w;
        }
    }
    __syncthreads();

    // Phase 2: out = h@W2^T + b2 (32 cols; warp covers 4 cols)
    int d0 = (tid >> 5) * 4;
    u64 acc2[4][2];
    {
        ulonglong2 b01 = *reinterpret_cast<const ulonglong2*>(db2 + d0);
#pragma unroll
        for (int r = 0; r < 4; ++r) { acc2[r][0] = b01.x; acc2[r][1] = b01.y; }
    }
    gemm2<64, 2, 32>(At, Bt, lane, d0, acc2);

#pragma unroll
    for (int r = 0; r < 4; ++r) {
        long grow = row0 + lane * 4 + r;
        long orow = grow;
        if (is_pred) orow = ((grow & 1023) << 8) | (grow >> 10);  // [p][b] -> b*P+p
        *reinterpret_cast<ulonglong2*>(xout + orow * Dn + d0) = make_ulonglong2(acc2[r][0], acc2[r][1]);
    }
}

// ---------------------------------------------------------------------------
extern "C" void kernel_launch(void* const* d_in, const int* in_sizes, int n_in,
                              void* d_out, int out_size) {
    const float* x   = (const float*)d_in[0];
    const float* ew1 = (const float*)d_in[1];
    const float* eb1 = (const float*)d_in[2];
    const float* ew2 = (const float*)d_in[3];
    const float* eb2 = (const float*)d_in[4];
    const float* dw1 = (const float*)d_in[5];
    const float* db1 = (const float*)d_in[6];
    const float* dw2 = (const float*)d_in[7];
    const float* db2 = (const float*)d_in[8];
    const float* Kw  = (const float*)d_in[9];
    float* out = (float*)d_out;

    kA1<<<1, 256>>>(Kw);
    kA2a<<<49, 256>>>();
    kA2b<<<192, 256>>>();

    kEnc<<<BS / 128, 256>>>(x, ew1, eb1, ew2, eb2, Kw, out);

    kPredZ<<<Pn * 8, 256>>>(out + OFF_Z);

    kDec<<<BS / 128, 256>>>(out + OFF_Z,    out + OFF_XREC,  dw1, db1, dw2, db2, 0);
    kDec<<<BS / 128, 256>>>(out + OFF_ZDYN, out + OFF_XDYN,  dw1, db1, dw2, db2, 0);
    kDec<<<(Bn * Pn) / 128, 256>>>(nullptr, out + OFF_XPRED, dw1, db1, dw2, db2, 1);
}

// round 5
// speedup vs baseline: 1.7019x; 1.1449x over previous
#include <cuda_runtime.h>

// DeepKoopman: B=1024,S=512,D=32,L=64,H=64,P=256
// Outputs: x_rec[B,S,D], x_dyn[B,S,D], x_pred[B,P,D], z[B,S,L], z_dyn[B,S,L]

namespace {
constexpr int Bn = 1024, Sn = 512, Dn = 32, Ln = 64, Hn = 64, Pn = 256;
constexpr int BS = Bn * Sn;                               // 524288
constexpr long OFF_XREC  = 0;
constexpr long OFF_XDYN  = (long)BS * Dn;
constexpr long OFF_XPRED = OFF_XDYN * 2;
constexpr long OFF_Z     = OFF_XPRED + (long)Bn * Pn * Dn;
constexpr long OFF_ZDYN  = OFF_Z + (long)BS * Ln;
}

// scratch (device globals; no allocation allowed)
__device__ float g_Mpow[256][4096];               // K^p row-major
__device__ float g_MpowT[256][4096];              // transposed
__device__ float g_zpred[(long)Bn * Pn * Ln];     // [P,B,L]
__device__ float g_zlastT[Ln * Bn];               // [L,B]
__device__ float g_ew1T[32 * 64];                 // [i][j]
__device__ float g_ew2T[64 * 64];                 // [j][l]
__device__ float g_KW2T[64 * 64];                 // [j][l'] of (K@W2)
__device__ float g_Kb2[64];                       // K@b2
__device__ float g_dw1T[64 * 64];                 // [l][j]
__device__ float g_dw2T[64 * 32];                 // [j][d]

using u64 = unsigned long long;

__device__ __forceinline__ u64 f2fma(u64 a, u64 b, u64 c) {
    u64 d; asm("fma.rn.f32x2 %0, %1, %2, %3;" : "=l"(d) : "l"(a), "l"(b), "l"(c)); return d;
}
__device__ __forceinline__ u64 packdup(float x) {
    u64 d; asm("mov.b64 %0, {%1, %2};" : "=l"(d) : "f"(x), "f"(x)); return d;
}
__device__ __forceinline__ float2 unpk(u64 v) {
    float2 r; asm("mov.b64 {%0, %1}, %2;" : "=f"(r.x), "=f"(r.y) : "l"(v)); return r;
}

// ---------------------------------------------------------------------------
// 4x4 transpose across lanes {l, l^8, l^16, l^24}; each lane holds one row (v0..v3).
// After: lane with index i=(l>>3)&3 holds column i. Ternary selects (no BSSY).
// ---------------------------------------------------------------------------
__device__ __forceinline__ void xpose44(float& v0, float& v1, float& v2, float& v3, int lane) {
    bool bi = (lane & 16) != 0;
    bool ii = (lane & 8) != 0;
    // step 1: block transpose (xor 16). bi=0 sends v2,v3; bi=1 sends v0,v1.
    float s0 = bi ? v0 : v2;
    float s1 = bi ? v1 : v3;
    float r0 = __shfl_xor_sync(0xffffffffu, s0, 16);
    float r1 = __shfl_xor_sync(0xffffffffu, s1, 16);
    v0 = bi ? r0 : v0;  v1 = bi ? r1 : v1;
    v2 = bi ? v2 : r0;  v3 = bi ? v3 : r1;
    // step 2: inner transpose (xor 8). ii=0 sends v1,v3; ii=1 sends v0,v2.
    float t0 = ii ? v0 : v1;
    float t1 = ii ? v2 : v3;
    float q0 = __shfl_xor_sync(0xffffffffu, t0, 8);
    float q1 = __shfl_xor_sync(0xffffffffu, t1, 8);
    v0 = ii ? q0 : v0;  v2 = ii ? q1 : v2;
    v1 = ii ? v1 : q0;  v3 = ii ? v3 : q1;
}

// Load 128 rows x KD cols (row-major, stride KD) -> At[k][128], conflict-free STS.128.
// 128 threads: warp w owns rows w*32..w*32+31.
template<int KD>
__device__ __forceinline__ void loadTileT(const float* __restrict__ src, long row0,
                                          float* At, int tid) {
    int w = tid >> 5, lane = tid & 31;
    int g = lane & 7, i = lane >> 3;
    int rband = w * 32 + g * 4;
    const float* rowp = src + (row0 + rband + i) * KD;
#pragma unroll
    for (int k0 = 0; k0 < KD; k0 += 4) {
        float4 v = *reinterpret_cast<const float4*>(rowp + k0);
        xpose44(v.x, v.y, v.z, v.w, lane);
        *reinterpret_cast<float4*>(At + (k0 + i) * 128 + rband) = v;  // k=k0+i, rows rband..+3
    }
}

// plain float4 copy global -> smem (n multiple of 512)
__device__ __forceinline__ void copyF4(const float* __restrict__ src, float* dst, int n, int tid) {
    const float4* s = reinterpret_cast<const float4*>(src);
    float4* d = reinterpret_cast<float4*>(dst);
    for (int i = tid; i < n / 4; i += 128) d[i] = s[i];
}

// ---------------------------------------------------------------------------
// GEMM core: rows lane*4..+3, cols c0..c0+2*NBP-1 (pairs). A conflict-free
// LDS.128; B warp-uniform LDS.128 (broadcast).
// ---------------------------------------------------------------------------
template<int KK, int NBP, int BSTR>
__device__ __forceinline__ void gemm2(const float* At, const float* Bt,
                                      int lane, int c0, u64 (&acc)[4][NBP]) {
#pragma unroll 8
    for (int k = 0; k < KK; ++k) {
        float4 a4 = *reinterpret_cast<const float4*>(At + k * 128 + lane * 4);
        u64 ad0 = packdup(a4.x), ad1 = packdup(a4.y), ad2 = packdup(a4.z), ad3 = packdup(a4.w);
        u64 bp[NBP];
#pragma unroll
        for (int ii = 0; ii < NBP / 2; ++ii) {
            ulonglong2 b = *reinterpret_cast<const ulonglong2*>(Bt + k * BSTR + c0 + 4 * ii);
            bp[2 * ii] = b.x; bp[2 * ii + 1] = b.y;
        }
#pragma unroll
        for (int j = 0; j < NBP; ++j) {
            acc[0][j] = f2fma(ad0, bp[j], acc[0][j]);
            acc[1][j] = f2fma(ad1, bp[j], acc[1][j]);
            acc[2][j] = f2fma(ad2, bp[j], acc[2][j]);
            acc[3][j] = f2fma(ad3, bp[j], acc[3][j]);
        }
    }
}

// transpose-store acc (with relu) into At[col][128]; conflict-free STS.128.
__device__ __forceinline__ void storeT8(float* At, int lane, int c0, const u64 (&acc)[4][8]) {
#pragma unroll
    for (int j = 0; j < 8; ++j) {
        float2 p0 = unpk(acc[0][j]), p1 = unpk(acc[1][j]), p2 = unpk(acc[2][j]), p3 = unpk(acc[3][j]);
        float4 lo = make_float4(fmaxf(p0.x, 0.f), fmaxf(p1.x, 0.f), fmaxf(p2.x, 0.f), fmaxf(p3.x, 0.f));
        float4 hi = make_float4(fmaxf(p0.y, 0.f), fmaxf(p1.y, 0.f), fmaxf(p2.y, 0.f), fmaxf(p3.y, 0.f));
        *reinterpret_cast<float4*>(At + (c0 + 2 * j)     * 128 + lane * 4) = lo;
        *reinterpret_cast<float4*>(At + (c0 + 2 * j + 1) * 128 + lane * 4) = hi;
    }
}

__device__ __forceinline__ void initBias(const float* b, int c0, u64 (&acc)[4][8]) {
    ulonglong2 b01 = *reinterpret_cast<const ulonglong2*>(b + c0);
    ulonglong2 b23 = *reinterpret_cast<const ulonglong2*>(b + c0 + 4);
    ulonglong2 b45 = *reinterpret_cast<const ulonglong2*>(b + c0 + 8);
    ulonglong2 b67 = *reinterpret_cast<const ulonglong2*>(b + c0 + 12);
#pragma unroll
    for (int r = 0; r < 4; ++r) {
        acc[r][0] = b01.x; acc[r][1] = b01.y; acc[r][2] = b23.x; acc[r][3] = b23.y;
        acc[r][4] = b45.x; acc[r][5] = b45.y; acc[r][6] = b67.x; acc[r][7] = b67.y;
    }
}

__device__ __forceinline__ void storeRows16(float* dst, long rstride, long row0, int lane,
                                            int c0, const u64 (&acc)[4][8]) {
#pragma unroll
    for (int r = 0; r < 4; ++r) {
        float* p = dst + (row0 + lane * 4 + r) * rstride + c0;
        *reinterpret_cast<ulonglong2*>(p)      = make_ulonglong2(acc[r][0], acc[r][1]);
        *reinterpret_cast<ulonglong2*>(p + 4)  = make_ulonglong2(acc[r][2], acc[r][3]);
        *reinterpret_cast<ulonglong2*>(p + 8)  = make_ulonglong2(acc[r][4], acc[r][5]);
        *reinterpret_cast<ulonglong2*>(p + 12) = make_ulonglong2(acc[r][6], acc[r][7]);
    }
}

// ---------------------------------------------------------------------------
// Setup: transpose weights once; compute KW2T and Kb2.
// ---------------------------------------------------------------------------
__global__ void __launch_bounds__(256) kSetup(
    const float* __restrict__ ew1, const float* __restrict__ ew2, const float* __restrict__ eb2,
    const float* __restrict__ dw1, const float* __restrict__ dw2, const float* __restrict__ Kw) {
    int tid = threadIdx.x;
    for (int o = tid; o < 2048; o += 256) g_ew1T[o] = ew1[(o & 63) * 32 + (o >> 6)];   // [i][j]
    for (int o = tid; o < 4096; o += 256) g_ew2T[o] = ew2[(o & 63) * 64 + (o >> 6)];   // [j][l]
    for (int o = tid; o < 4096; o += 256) g_dw1T[o] = dw1[(o & 63) * 64 + (o >> 6)];   // [l][j]
    for (int o = tid; o < 2048; o += 256) g_dw2T[o] = dw2[(o & 31) * 64 + (o >> 5)];   // [j][d]
    for (int o = tid; o < 4096; o += 256) {            // KW2T[j][l'] = sum_l ew2[l][j]*Kw[l'][l]
        int j = o >> 6, lp = o & 63;
        float s = 0.f;
#pragma unroll 8
        for (int l = 0; l < 64; ++l) s += ew2[l * 64 + j] * Kw[lp * 64 + l];
        g_KW2T[o] = s;
    }
    if (tid < 64) {
        float s = 0.f;
        for (int l = 0; l < 64; ++l) s += Kw[tid * 64 + l] * eb2[l];
        g_Kb2[tid] = s;
    }
}

// ---------------------------------------------------------------------------
// Koopman power table (chain + parallel fill + batch transpose)
// ---------------------------------------------------------------------------
__device__ __forceinline__ void mm64_step(const float* sA, float* sB, float* gout, int tid) {
    float r[16];
#pragma unroll
    for (int t = 0; t < 16; ++t) {
        int o = tid + t * 256;
        int row = o >> 6, c = o & 63;
        float acc = 0.f;
#pragma unroll 8
        for (int k = 0; k < 64; ++k) acc += sA[row * 64 + k] * sB[k * 64 + c];
        r[t] = acc;
    }
    __syncthreads();
#pragma unroll
    for (int t = 0; t < 16; ++t) {
        int o = tid + t * 256;
        sB[o] = r[t];
        gout[o] = r[t];
    }
    __syncthreads();
}

__global__ void __launch_bounds__(256) kA1(const float* __restrict__ Kw) {
    __shared__ float sA[4096], sB[4096];
    int tid = threadIdx.x;
#pragma unroll
    for (int t = 0; t < 16; ++t) {
        int o = tid + t * 256;
        float v = Kw[o];
        sA[o] = v; sB[o] = v;
        g_Mpow[0][o] = v;
    }
    __syncthreads();
    for (int p = 2; p <= 8; ++p) mm64_step(sA, sB, g_Mpow[p - 1], tid);     // -> K^8
#pragma unroll
    for (int t = 0; t < 16; ++t) { int o = tid + t * 256; sA[o] = sB[o]; }
    __syncthreads();
    for (int q = 2; q <= 8; ++q) mm64_step(sA, sB, g_Mpow[8 * q - 1], tid); // -> K^64
#pragma unroll
    for (int t = 0; t < 16; ++t) { int o = tid + t * 256; sA[o] = sB[o]; }
    __syncthreads();
    mm64_step(sA, sB, g_Mpow[127], tid);  // K^128
    mm64_step(sA, sB, g_Mpow[191], tid);  // K^192
}

__device__ __forceinline__ void mm64_gg(const float* __restrict__ ga, const float* __restrict__ gb,
                                        float* __restrict__ gd, float* sA, float* sB, int tid) {
#pragma unroll
    for (int t = 0; t < 16; ++t) {
        int o = tid + t * 256;
        sA[o] = ga[o]; sB[o] = gb[o];
    }
    __syncthreads();
#pragma unroll
    for (int t = 0; t < 16; ++t) {
        int o = tid + t * 256;
        int row = o >> 6, c = o & 63;
        float acc = 0.f;
#pragma unroll 8
        for (int k = 0; k < 64; ++k) acc += sA[row * 64 + k] * sB[k * 64 + c];
        gd[o] = acc;
    }
}

__global__ void __launch_bounds__(256) kA2a() {
    int q = blockIdx.x / 7 + 1, r = blockIdx.x % 7 + 1;
    __shared__ float sA[4096], sB[4096];
    mm64_gg(g_Mpow[8 * q - 1], g_Mpow[r - 1], g_Mpow[8 * q + r - 1], sA, sB, threadIdx.x);
}

__global__ void __launch_bounds__(256) kA2b() {
    int t = blockIdx.x / 64 + 1, m = blockIdx.x % 64 + 1;
    if (m == 64 && t <= 2) return;
    __shared__ float sA[4096], sB[4096];
    mm64_gg(g_Mpow[64 * t - 1], g_Mpow[m - 1], g_Mpow[64 * t + m - 1], sA, sB, threadIdx.x);
}

__global__ void __launch_bounds__(256) kAT() {   // MpowT[p] = Mpow[p]^T (256 blocks)
    __shared__ float s[4096];
    int p = blockIdx.x, tid = threadIdx.x;
    for (int o = tid; o < 4096; o += 256) s[o] = g_Mpow[p][o];
    __syncthreads();
    for (int o = tid; o < 4096; o += 256) g_MpowT[p][o] = s[(o & 63) * 64 + (o >> 6)];
}

// ---------------------------------------------------------------------------
// Encoder: x -> z, z_dyn.  128 threads, tile 128 rows x 64 cols, 16 cols/warp.
// z_dyn fused as h @ (K*W2)^T + K*b2  (no z re-transpose).
// ---------------------------------------------------------------------------
__global__ void __launch_bounds__(128) kEnc(
    const float* __restrict__ x,
    const float* __restrict__ eb1, const float* __restrict__ eb2,
    float* __restrict__ out)
{
    __shared__ float At[64 * 128];   // 32KB
    __shared__ float Bt[64 * 64];    // 16KB
    int tid = threadIdx.x;
    int lane = tid & 31;
    int c0 = (tid >> 5) * 16;
    long row0 = (long)blockIdx.x * 128;

    loadTileT<32>(x, row0, At, tid);            // x tile -> At[k<32][128]
    copyF4(g_ew1T, Bt, 2048, tid);              // [i][j]
    __syncthreads();

    // Phase 1: h = relu(x@W1^T + b1)
    u64 acc[4][8];
    initBias(eb1, c0, acc);
    gemm2<32, 8, 64>(At, Bt, lane, c0, acc);
    __syncthreads();

    storeT8(At, lane, c0, acc);                 // h (relu) -> At[j][128]
    copyF4(g_ew2T, Bt, 4096, tid);              // [j][l]
    __syncthreads();

    // Phase 2: z = h@W2^T + b2
    initBias(eb2, c0, acc);
    gemm2<64, 8, 64>(At, Bt, lane, c0, acc);
    storeRows16(out + OFF_Z, Ln, row0, lane, c0, acc);
    __syncthreads();

    copyF4(g_KW2T, Bt, 4096, tid);              // [j][l']
    __syncthreads();

    // Phase 3: z_dyn = h@(K W2)^T + K b2
    initBias(g_Kb2, c0, acc);
    gemm2<64, 8, 64>(At, Bt, lane, c0, acc);
    storeRows16(out + OFF_ZDYN, Ln, row0, lane, c0, acc);
}

// ---------------------------------------------------------------------------
// z_last transpose: g_zlastT[l][b] = z[b][S-1][l]
// ---------------------------------------------------------------------------
__global__ void __launch_bounds__(256) kT(const float* __restrict__ z) {
    int o = blockIdx.x * 256 + threadIdx.x;     // o = b*64 + l
    int b = o >> 6, l = o & 63;
    g_zlastT[l * Bn + b] = z[((long)b * Sn + (Sn - 1)) * Ln + l];
}

// ---------------------------------------------------------------------------
// Pred rollout: g_zpred[p][b] = z_last[b] @ (K^(p+1))^T.  Transpose-free loads.
// grid = 256*8, 128 threads.
// ---------------------------------------------------------------------------
__global__ void __launch_bounds__(128) kPredZ() {
    __shared__ float At[64 * 128];
    __shared__ float Bt[64 * 64];
    int tid = threadIdx.x;
    int lane = tid & 31;
    int c0 = (tid >> 5) * 16;
    int p = blockIdx.x >> 3;
    int b0 = (blockIdx.x & 7) * 128;

    // At[k][128] <- g_zlastT[k][b0..b0+127]
    for (int u = tid; u < 64 * 32; u += 128) {
        int k = u >> 5, cq = (u & 31) * 4;
        *reinterpret_cast<float4*>(At + k * 128 + cq) =
            *reinterpret_cast<const float4*>(g_zlastT + k * Bn + b0 + cq);
    }
    copyF4(g_MpowT[p], Bt, 4096, tid);
    __syncthreads();

    u64 acc[4][8];
#pragma unroll
    for (int j = 0; j < 8; ++j)
#pragma unroll
        for (int r = 0; r < 4; ++r) acc[r][j] = 0ull;
    gemm2<64, 8, 64>(At, Bt, lane, c0, acc);
    storeRows16(g_zpred, Ln, (long)p * Bn + b0, lane, c0, acc);
}

// ---------------------------------------------------------------------------
// Combined decoder: 3 segments (z->x_rec, z_dyn->x_dyn, z_pred->x_pred).
// 128 threads; phase1 16 cols/warp, phase2 8 cols/warp.
// ---------------------------------------------------------------------------
__global__ void __launch_bounds__(128) kDecAll(
    float* __restrict__ out,
    const float* __restrict__ db1, const float* __restrict__ db2)
{
    __shared__ float At[64 * 128];
    __shared__ float Bt[64 * 64];
    int tid = threadIdx.x;
    int lane = tid & 31;
    int c0 = (tid >> 5) * 16;
    int bid = blockIdx.x;

    const float* zin;
    float* xout;
    long row0;
    int is_pred = 0;
    if (bid < 4096)      { zin = out + OFF_Z;    xout = out + OFF_XREC;  row0 = (long)bid * 128; }
    else if (bid < 8192) { zin = out + OFF_ZDYN; xout = out + OFF_XDYN;  row0 = (long)(bid - 4096) * 128; }
    else                 { zin = g_zpred;        xout = out + OFF_XPRED; row0 = (long)(bid - 8192) * 128; is_pred = 1; }

    loadTileT<64>(zin, row0, At, tid);
    copyF4(g_dw1T, Bt, 4096, tid);
    __syncthreads();

    // Phase 1: h = relu(z@W1^T + b1)
    u64 acc[4][8];
    initBias(db1, c0, acc);
    gemm2<64, 8, 64>(At, Bt, lane, c0, acc);
    __syncthreads();

    storeT8(At, lane, c0, acc);                 // h -> At[j][128]
    copyF4(g_dw2T, Bt, 2048, tid);              // [j][d] stride 32
    __syncthreads();

    // Phase 2: x = h@W2^T + b2 (32 cols; 8 cols/warp)
    int d0 = (tid >> 5) * 8;
    u64 acc2[4][4];
    {
        ulonglong2 b01 = *reinterpret_cast<const ulonglong2*>(db2 + d0);
        ulonglong2 b23 = *reinterpret_cast<const ulonglong2*>(db2 + d0 + 4);
#pragma unroll
        for (int r = 0; r < 4; ++r) { acc2[r][0] = b01.x; acc2[r][1] = b01.y; acc2[r][2] = b23.x; acc2[r][3] = b23.y; }
    }
    gemm2<64, 4, 32>(At, Bt, lane, d0, acc2);

#pragma unroll
    for (int r = 0; r < 4; ++r) {
        long grow = row0 + lane * 4 + r;
        long orow = grow;
        if (is_pred) orow = ((grow & 1023) << 8) | (grow >> 10);  // [p][b] -> b*P+p
        float* pdst = xout + orow * Dn + d0;
        *reinterpret_cast<ulonglong2*>(pdst)     = make_ulonglong2(acc2[r][0], acc2[r][1]);
        *reinterpret_cast<ulonglong2*>(pdst + 4) = make_ulonglong2(acc2[r][2], acc2[r][3]);
    }
}

// ---------------------------------------------------------------------------
extern "C" void kernel_launch(void* const* d_in, const int* in_sizes, int n_in,
                              void* d_out, int out_size) {
    const float* x   = (const float*)d_in[0];
    const float* ew1 = (const float*)d_in[1];
    const float* eb1 = (const float*)d_in[2];
    const float* ew2 = (const float*)d_in[3];
    const float* eb2 = (const float*)d_in[4];
    const float* dw1 = (const float*)d_in[5];
    const float* db1 = (const float*)d_in[6];
    const float* dw2 = (const float*)d_in[7];
    const float* db2 = (const float*)d_in[8];
    const float* Kw  = (const float*)d_in[9];
    float* out = (float*)d_out;

    kSetup<<<1, 256>>>(ew1, ew2, eb2, dw1, dw2, Kw);
    kA1<<<1, 256>>>(Kw);
    kA2a<<<49, 256>>>();
    kA2b<<<192, 256>>>();
    kAT<<<256, 256>>>();

    kEnc<<<BS / 128, 128>>>(x, eb1, eb2, out);

    kT<<<256, 256>>>(out + OFF_Z);
    kPredZ<<<Pn * 8, 128>>>();

    kDecAll<<<BS / 128 * 2 + (Bn * Pn) / 128, 128>>>(out, db1, db2);
}

// round 6
// speedup vs baseline: 1.7028x; 1.0006x over previous
#include <cuda_runtime.h>

// DeepKoopman: B=1024,S=512,D=32,L=64,H=64,P=256
// Outputs: x_rec[B,S,D], x_dyn[B,S,D], x_pred[B,P,D], z[B,S,L], z_dyn[B,S,L]

namespace {
constexpr int Bn = 1024, Sn = 512, Dn = 32, Ln = 64, Hn = 64, Pn = 256;
constexpr int BS = Bn * Sn;                               // 524288
constexpr long OFF_XREC  = 0;
constexpr long OFF_XDYN  = (long)BS * Dn;
constexpr long OFF_XPRED = OFF_XDYN * 2;
constexpr long OFF_Z     = OFF_XPRED + (long)Bn * Pn * Dn;
constexpr long OFF_ZDYN  = OFF_Z + (long)BS * Ln;
}

// scratch (device globals; no allocation allowed)
__device__ float g_Mpow[256][4096];               // K^p row-major
__device__ float g_MpowT[256][4096];              // transposed
__device__ float g_zpred[(long)Bn * Pn * Ln];     // [P,B,L]
__device__ float g_zlastT[Ln * Bn];               // [L,B]
__device__ float g_ew1T[32 * 64];                 // [i][j]
__device__ float g_ew2T[64 * 64];                 // [j][l]
__device__ float g_KW2T[64 * 64];                 // [j][l'] of (K@W2)
__device__ float g_Kb2[64];                       // K@b2
__device__ float g_dw1T[64 * 64];                 // [l][j]
__device__ float g_dw2T[64 * 32];                 // [j][d]

using u64 = unsigned long long;

__device__ __forceinline__ u64 f2fma(u64 a, u64 b, u64 c) {
    u64 d; asm("fma.rn.f32x2 %0, %1, %2, %3;" : "=l"(d) : "l"(a), "l"(b), "l"(c)); return d;
}
__device__ __forceinline__ u64 packdup(float x) {
    u64 d; asm("mov.b64 %0, {%1, %2};" : "=l"(d) : "f"(x), "f"(x)); return d;
}
__device__ __forceinline__ float2 unpk(u64 v) {
    float2 r; asm("mov.b64 {%0, %1}, %2;" : "=f"(r.x), "=f"(r.y) : "l"(v)); return r;
}

// ---------------------------------------------------------------------------
// 4x4 transpose across lanes {l, l^8, l^16, l^24}; each lane holds one row (v0..v3).
// After: lane with index i=(l>>3)&3 holds column i. Ternary selects (no BSSY).
// ---------------------------------------------------------------------------
__device__ __forceinline__ void xpose44(float& v0, float& v1, float& v2, float& v3, int lane) {
    bool bi = (lane & 16) != 0;
    bool ii = (lane & 8) != 0;
    // step 1: block transpose (xor 16). bi=0 sends v2,v3; bi=1 sends v0,v1.
    float s0 = bi ? v0 : v2;
    float s1 = bi ? v1 : v3;
    float r0 = __shfl_xor_sync(0xffffffffu, s0, 16);
    float r1 = __shfl_xor_sync(0xffffffffu, s1, 16);
    v0 = bi ? r0 : v0;  v1 = bi ? r1 : v1;
    v2 = bi ? v2 : r0;  v3 = bi ? v3 : r1;
    // step 2: inner transpose (xor 8). ii=0 sends v1,v3; ii=1 sends v0,v2.
    float t0 = ii ? v0 : v1;
    float t1 = ii ? v2 : v3;
    float q0 = __shfl_xor_sync(0xffffffffu, t0, 8);
    float q1 = __shfl_xor_sync(0xffffffffu, t1, 8);
    v0 = ii ? q0 : v0;  v2 = ii ? q1 : v2;
    v1 = ii ? v1 : q0;  v3 = ii ? v3 : q1;
}

// Load 128 rows x KD cols (row-major, stride KD) -> At[k][128], conflict-free STS.128.
// 128 threads: warp w owns rows w*32..w*32+31.
template<int KD>
__device__ __forceinline__ void loadTileT(const float* __restrict__ src, long row0,
                                          float* At, int tid) {
    int w = tid >> 5, lane = tid & 31;
    int g = lane & 7, i = lane >> 3;
    int rband = w * 32 + g * 4;
    const float* rowp = src + (row0 + rband + i) * KD;
#pragma unroll
    for (int k0 = 0; k0 < KD; k0 += 4) {
        float4 v = *reinterpret_cast<const float4*>(rowp + k0);
        xpose44(v.x, v.y, v.z, v.w, lane);
        *reinterpret_cast<float4*>(At + (k0 + i) * 128 + rband) = v;  // k=k0+i, rows rband..+3
    }
}

// plain float4 copy global -> smem (n multiple of 512)
__device__ __forceinline__ void copyF4(const float* __restrict__ src, float* dst, int n, int tid) {
    const float4* s = reinterpret_cast<const float4*>(src);
    float4* d = reinterpret_cast<float4*>(dst);
    for (int i = tid; i < n / 4; i += 128) d[i] = s[i];
}

// ---------------------------------------------------------------------------
// GEMM core: rows lane*4..+3, cols c0..c0+2*NBP-1 (pairs). A conflict-free
// LDS.128; B warp-uniform LDS.128 (broadcast).
// ---------------------------------------------------------------------------
template<int KK, int NBP, int BSTR>
__device__ __forceinline__ void gemm2(const float* At, const float* Bt,
                                      int lane, int c0, u64 (&acc)[4][NBP]) {
#pragma unroll 8
    for (int k = 0; k < KK; ++k) {
        float4 a4 = *reinterpret_cast<const float4*>(At + k * 128 + lane * 4);
        u64 ad0 = packdup(a4.x), ad1 = packdup(a4.y), ad2 = packdup(a4.z), ad3 = packdup(a4.w);
        u64 bp[NBP];
#pragma unroll
        for (int ii = 0; ii < NBP / 2; ++ii) {
            ulonglong2 b = *reinterpret_cast<const ulonglong2*>(Bt + k * BSTR + c0 + 4 * ii);
            bp[2 * ii] = b.x; bp[2 * ii + 1] = b.y;
        }
#pragma unroll
        for (int j = 0; j < NBP; ++j) {
            acc[0][j] = f2fma(ad0, bp[j], acc[0][j]);
            acc[1][j] = f2fma(ad1, bp[j], acc[1][j]);
            acc[2][j] = f2fma(ad2, bp[j], acc[2][j]);
            acc[3][j] = f2fma(ad3, bp[j], acc[3][j]);
        }
    }
}

// transpose-store acc (with relu) into At[col][128]; conflict-free STS.128.
__device__ __forceinline__ void storeT8(float* At, int lane, int c0, const u64 (&acc)[4][8]) {
#pragma unroll
    for (int j = 0; j < 8; ++j) {
        float2 p0 = unpk(acc[0][j]), p1 = unpk(acc[1][j]), p2 = unpk(acc[2][j]), p3 = unpk(acc[3][j]);
        float4 lo = make_float4(fmaxf(p0.x, 0.f), fmaxf(p1.x, 0.f), fmaxf(p2.x, 0.f), fmaxf(p3.x, 0.f));
        float4 hi = make_float4(fmaxf(p0.y, 0.f), fmaxf(p1.y, 0.f), fmaxf(p2.y, 0.f), fmaxf(p3.y, 0.f));
        *reinterpret_cast<float4*>(At + (c0 + 2 * j)     * 128 + lane * 4) = lo;
        *reinterpret_cast<float4*>(At + (c0 + 2 * j + 1) * 128 + lane * 4) = hi;
    }
}

__device__ __forceinline__ void initBias(const float* b, int c0, u64 (&acc)[4][8]) {
    ulonglong2 b01 = *reinterpret_cast<const ulonglong2*>(b + c0);
    ulonglong2 b23 = *reinterpret_cast<const ulonglong2*>(b + c0 + 4);
    ulonglong2 b45 = *reinterpret_cast<const ulonglong2*>(b + c0 + 8);
    ulonglong2 b67 = *reinterpret_cast<const ulonglong2*>(b + c0 + 12);
#pragma unroll
    for (int r = 0; r < 4; ++r) {
        acc[r][0] = b01.x; acc[r][1] = b01.y; acc[r][2] = b23.x; acc[r][3] = b23.y;
        acc[r][4] = b45.x; acc[r][5] = b45.y; acc[r][6] = b67.x; acc[r][7] = b67.y;
    }
}

__device__ __forceinline__ void storeRows16(float* dst, long rstride, long row0, int lane,
                                            int c0, const u64 (&acc)[4][8]) {
#pragma unroll
    for (int r = 0; r < 4; ++r) {
        float* p = dst + (row0 + lane * 4 + r) * rstride + c0;
        *reinterpret_cast<ulonglong2*>(p)      = make_ulonglong2(acc[r][0], acc[r][1]);
        *reinterpret_cast<ulonglong2*>(p + 4)  = make_ulonglong2(acc[r][2], acc[r][3]);
        *reinterpret_cast<ulonglong2*>(p + 8)  = make_ulonglong2(acc[r][4], acc[r][5]);
        *reinterpret_cast<ulonglong2*>(p + 12) = make_ulonglong2(acc[r][6], acc[r][7]);
    }
}

// ---------------------------------------------------------------------------
// Setup: transpose weights once; compute KW2T and Kb2.
// ---------------------------------------------------------------------------
__global__ void __launch_bounds__(256) kSetup(
    const float* __restrict__ ew1, const float* __restrict__ ew2, const float* __restrict__ eb2,
    const float* __restrict__ dw1, const float* __restrict__ dw2, const float* __restrict__ Kw) {
    int tid = threadIdx.x;
    for (int o = tid; o < 2048; o += 256) g_ew1T[o] = ew1[(o & 63) * 32 + (o >> 6)];   // [i][j]
    for (int o = tid; o < 4096; o += 256) g_ew2T[o] = ew2[(o & 63) * 64 + (o >> 6)];   // [j][l]
    for (int o = tid; o < 4096; o += 256) g_dw1T[o] = dw1[(o & 63) * 64 + (o >> 6)];   // [l][j]
    for (int o = tid; o < 2048; o += 256) g_dw2T[o] = dw2[(o & 31) * 64 + (o >> 5)];   // [j][d]
    for (int o = tid; o < 4096; o += 256) {            // KW2T[j][l'] = sum_l ew2[l][j]*Kw[l'][l]
        int j = o >> 6, lp = o & 63;
        float s = 0.f;
#pragma unroll 8
        for (int l = 0; l < 64; ++l) s += ew2[l * 64 + j] * Kw[lp * 64 + l];
        g_KW2T[o] = s;
    }
    if (tid < 64) {
        float s = 0.f;
        for (int l = 0; l < 64; ++l) s += Kw[tid * 64 + l] * eb2[l];
        g_Kb2[tid] = s;
    }
}

// ---------------------------------------------------------------------------
// Koopman power table (chain + parallel fill + batch transpose)
// ---------------------------------------------------------------------------
__device__ __forceinline__ void mm64_step(const float* sA, float* sB, float* gout, int tid) {
    float r[16];
#pragma unroll
    for (int t = 0; t < 16; ++t) {
        int o = tid + t * 256;
        int row = o >> 6, c = o & 63;
        float acc = 0.f;
#pragma unroll 8
        for (int k = 0; k < 64; ++k) acc += sA[row * 64 + k] * sB[k * 64 + c];
        r[t] = acc;
    }
    __syncthreads();
#pragma unroll
    for (int t = 0; t < 16; ++t) {
        int o = tid + t * 256;
        sB[o] = r[t];
        gout[o] = r[t];
    }
    __syncthreads();
}

__global__ void __launch_bounds__(256) kA1(const float* __restrict__ Kw) {
    __shared__ float sA[4096], sB[4096];
    int tid = threadIdx.x;
#pragma unroll
    for (int t = 0; t < 16; ++t) {
        int o = tid + t * 256;
        float v = Kw[o];
        sA[o] = v; sB[o] = v;
        g_Mpow[0][o] = v;
    }
    __syncthreads();
    for (int p = 2; p <= 8; ++p) mm64_step(sA, sB, g_Mpow[p - 1], tid);     // -> K^8
#pragma unroll
    for (int t = 0; t < 16; ++t) { int o = tid + t * 256; sA[o] = sB[o]; }
    __syncthreads();
    for (int q = 2; q <= 8; ++q) mm64_step(sA, sB, g_Mpow[8 * q - 1], tid); // -> K^64
#pragma unroll
    for (int t = 0; t < 16; ++t) { int o = tid + t * 256; sA[o] = sB[o]; }
    __syncthreads();
    mm64_step(sA, sB, g_Mpow[127], tid);  // K^128
    mm64_step(sA, sB, g_Mpow[191], tid);  // K^192
}

__device__ __forceinline__ void mm64_gg(const float* __restrict__ ga, const float* __restrict__ gb,
                                        float* __restrict__ gd, float* sA, float* sB, int tid) {
#pragma unroll
    for (int t = 0; t < 16; ++t) {
        int o = tid + t * 256;
        sA[o] = ga[o]; sB[o] = gb[o];
    }
    __syncthreads();
#pragma unroll
    for (int t = 0; t < 16; ++t) {
        int o = tid + t * 256;
        int row = o >> 6, c = o & 63;
        float acc = 0.f;
#pragma unroll 8
        for (int k = 0; k < 64; ++k) acc += sA[row * 64 + k] * sB[k * 64 + c];
        gd[o] = acc;
    }
}

__global__ void __launch_bounds__(256) kA2a() {
    int q = blockIdx.x / 7 + 1, r = blockIdx.x % 7 + 1;
    __shared__ float sA[4096], sB[4096];
    mm64_gg(g_Mpow[8 * q - 1], g_Mpow[r - 1], g_Mpow[8 * q + r - 1], sA, sB, threadIdx.x);
}

__global__ void __launch_bounds__(256) kA2b() {
    int t = blockIdx.x / 64 + 1, m = blockIdx.x % 64 + 1;
    if (m == 64 && t <= 2) return;
    __shared__ float sA[4096], sB[4096];
    mm64_gg(g_Mpow[64 * t - 1], g_Mpow[m - 1], g_Mpow[64 * t + m - 1], sA, sB, threadIdx.x);
}

__global__ void __launch_bounds__(256) kAT() {   // MpowT[p] = Mpow[p]^T (256 blocks)
    __shared__ float s[4096];
    int p = blockIdx.x, tid = threadIdx.x;
    for (int o = tid; o < 4096; o += 256) s[o] = g_Mpow[p][o];
    __syncthreads();
    for (int o = tid; o < 4096; o += 256) g_MpowT[p][o] = s[(o & 63) * 64 + (o >> 6)];
}

// ---------------------------------------------------------------------------
// Encoder: x -> z, z_dyn.  128 threads, tile 128 rows x 64 cols, 16 cols/warp.
// z_dyn fused as h @ (K*W2)^T + K*b2  (no z re-transpose).
// ---------------------------------------------------------------------------
__global__ void __launch_bounds__(128) kEnc(
    const float* __restrict__ x,
    const float* __restrict__ eb1, const float* __restrict__ eb2,
    float* __restrict__ out)
{
    __shared__ float At[64 * 128];   // 32KB
    __shared__ float Bt[64 * 64];    // 16KB
    int tid = threadIdx.x;
    int lane = tid & 31;
    int c0 = (tid >> 5) * 16;
    long row0 = (long)blockIdx.x * 128;

    loadTileT<32>(x, row0, At, tid);            // x tile -> At[k<32][128]
    copyF4(g_ew1T, Bt, 2048, tid);              // [i][j]
    __syncthreads();

    // Phase 1: h = relu(x@W1^T + b1)
    u64 acc[4][8];
    initBias(eb1, c0, acc);
    gemm2<32, 8, 64>(At, Bt, lane, c0, acc);
    __syncthreads();

    storeT8(At, lane, c0, acc);                 // h (relu) -> At[j][128]
    copyF4(g_ew2T, Bt, 4096, tid);              // [j][l]
    __syncthreads();

    // Phase 2: z = h@W2^T + b2
    initBias(eb2, c0, acc);
    gemm2<64, 8, 64>(At, Bt, lane, c0, acc);
    storeRows16(out + OFF_Z, Ln, row0, lane, c0, acc);
    __syncthreads();

    copyF4(g_KW2T, Bt, 4096, tid);              // [j][l']
    __syncthreads();

    // Phase 3: z_dyn = h@(K W2)^T + K b2
    initBias(g_Kb2, c0, acc);
    gemm2<64, 8, 64>(At, Bt, lane, c0, acc);
    storeRows16(out + OFF_ZDYN, Ln, row0, lane, c0, acc);
}

// ---------------------------------------------------------------------------
// z_last transpose: g_zlastT[l][b] = z[b][S-1][l]
// ---------------------------------------------------------------------------
__global__ void __launch_bounds__(256) kT(const float* __restrict__ z) {
    int o = blockIdx.x * 256 + threadIdx.x;     // o = b*64 + l
    int b = o >> 6, l = o & 63;
    g_zlastT[l * Bn + b] = z[((long)b * Sn + (Sn - 1)) * Ln + l];
}

// ---------------------------------------------------------------------------
// Pred rollout: g_zpred[p][b] = z_last[b] @ (K^(p+1))^T.  Transpose-free loads.
// grid = 256*8, 128 threads.
// ---------------------------------------------------------------------------
__global__ void __launch_bounds__(128) kPredZ() {
    __shared__ float At[64 * 128];
    __shared__ float Bt[64 * 64];
    int tid = threadIdx.x;
    int lane = tid & 31;
    int c0 = (tid >> 5) * 16;
    int p = blockIdx.x >> 3;
    int b0 = (blockIdx.x & 7) * 128;

    // At[k][128] <- g_zlastT[k][b0..b0+127]
    for (int u = tid; u < 64 * 32; u += 128) {
        int k = u >> 5, cq = (u & 31) * 4;
        *reinterpret_cast<float4*>(At + k * 128 + cq) =
            *reinterpret_cast<const float4*>(g_zlastT + k * Bn + b0 + cq);
    }
    copyF4(g_MpowT[p], Bt, 4096, tid);
    __syncthreads();

    u64 acc[4][8];
#pragma unroll
    for (int j = 0; j < 8; ++j)
#pragma unroll
        for (int r = 0; r < 4; ++r) acc[r][j] = 0ull;
    gemm2<64, 8, 64>(At, Bt, lane, c0, acc);
    storeRows16(g_zpred, Ln, (long)p * Bn + b0, lane, c0, acc);
}

// ---------------------------------------------------------------------------
// Combined decoder: 3 segments (z->x_rec, z_dyn->x_dyn, z_pred->x_pred).
// 128 threads; phase1 16 cols/warp, phase2 8 cols/warp.
// ---------------------------------------------------------------------------
__global__ void __launch_bounds__(128) kDecAll(
    float* __restrict__ out,
    const float* __restrict__ db1, const float* __restrict__ db2)
{
    __shared__ float At[64 * 128];
    __shared__ float Bt[64 * 64];
    int tid = threadIdx.x;
    int lane = tid & 31;
    int c0 = (tid >> 5) * 16;
    int bid = blockIdx.x;

    const float* zin;
    float* xout;
    long row0;
    int is_pred = 0;
    if (bid < 4096)      { zin = out + OFF_Z;    xout = out + OFF_XREC;  row0 = (long)bid * 128; }
    else if (bid < 8192) { zin = out + OFF_ZDYN; xout = out + OFF_XDYN;  row0 = (long)(bid - 4096) * 128; }
    else                 { zin = g_zpred;        xout = out + OFF_XPRED; row0 = (long)(bid - 8192) * 128; is_pred = 1; }

    loadTileT<64>(zin, row0, At, tid);
    copyF4(g_dw1T, Bt, 4096, tid);
    __syncthreads();

    // Phase 1: h = relu(z@W1^T + b1)
    u64 acc[4][8];
    initBias(db1, c0, acc);
    gemm2<64, 8, 64>(At, Bt, lane, c0, acc);
    __syncthreads();

    storeT8(At, lane, c0, acc);                 // h -> At[j][128]
    copyF4(g_dw2T, Bt, 2048, tid);              // [j][d] stride 32
    __syncthreads();

    // Phase 2: x = h@W2^T + b2 (32 cols; 8 cols/warp)
    int d0 = (tid >> 5) * 8;
    u64 acc2[4][4];
    {
        ulonglong2 b01 = *reinterpret_cast<const ulonglong2*>(db2 + d0);
        ulonglong2 b23 = *reinterpret_cast<const ulonglong2*>(db2 + d0 + 4);
#pragma unroll
        for (int r = 0; r < 4; ++r) { acc2[r][0] = b01.x; acc2[r][1] = b01.y; acc2[r][2] = b23.x; acc2[r][3] = b23.y; }
    }
    gemm2<64, 4, 32>(At, Bt, lane, d0, acc2);

#pragma unroll
    for (int r = 0; r < 4; ++r) {
        long grow = row0 + lane * 4 + r;
        long orow = grow;
        if (is_pred) orow = ((grow & 1023) << 8) | (grow >> 10);  // [p][b] -> b*P+p
        float* pdst = xout + orow * Dn + d0;
        *reinterpret_cast<ulonglong2*>(pdst)     = make_ulonglong2(acc2[r][0], acc2[r][1]);
        *reinterpret_cast<ulonglong2*>(pdst + 4) = make_ulonglong2(acc2[r][2], acc2[r][3]);
    }
}

// ---------------------------------------------------------------------------
extern "C" void kernel_launch(void* const* d_in, const int* in_sizes, int n_in,
                              void* d_out, int out_size) {
    const float* x   = (const float*)d_in[0];
    const float* ew1 = (const float*)d_in[1];
    const float* eb1 = (const float*)d_in[2];
    const float* ew2 = (const float*)d_in[3];
    const float* eb2 = (const float*)d_in[4];
    const float* dw1 = (const float*)d_in[5];
    const float* db1 = (const float*)d_in[6];
    const float* dw2 = (const float*)d_in[7];
    const float* db2 = (const float*)d_in[8];
    const float* Kw  = (const float*)d_in[9];
    float* out = (float*)d_out;

    kSetup<<<1, 256>>>(ew1, ew2, eb2, dw1, dw2, Kw);
    kA1<<<1, 256>>>(Kw);
    kA2a<<<49, 256>>>();
    kA2b<<<192, 256>>>();
    kAT<<<256, 256>>>();

    kEnc<<<BS / 128, 128>>>(x, eb1, eb2, out);

    kT<<<256, 256>>>(out + OFF_Z);
    kPredZ<<<Pn * 8, 128>>>();

    kDecAll<<<BS / 128 * 2 + (Bn * Pn) / 128, 128>>>(out, db1, db2);
}